// round 1
// baseline (speedup 1.0000x reference)
#include <cuda_runtime.h>

#define BB 128
#define CC 3
#define HH 256
#define WW 256
#define SHIFT 32
#define HW (HH*WW)      // 65536
#define CHW (CC*HW)     // 196608

__device__ float g_sum[BB];

__global__ void zero_sums_kernel() {
    if (threadIdx.x < BB) g_sum[threadIdx.x] = 0.f;
}

// grid = BB * RBLKS blocks, 256 threads. Each block reduces a contiguous chunk
// of one image, one atomicAdd per block.
#define RBLKS 32
__global__ void reduce_kernel(const float* __restrict__ imgs) {
    int b   = blockIdx.x / RBLKS;
    int blk = blockIdx.x % RBLKS;
    const float4* p = (const float4*)(imgs + (size_t)b * CHW);
    const int n4      = CHW / 4;        // 49152
    const int per_blk = n4 / RBLKS;     // 1536
    int base = blk * per_blk;
    float s = 0.f;
    #pragma unroll 6
    for (int i = threadIdx.x; i < per_blk; i += 256) {
        float4 v = p[base + i];
        s += (v.x + v.y) + (v.z + v.w);
    }
    #pragma unroll
    for (int o = 16; o; o >>= 1) s += __shfl_down_sync(0xffffffffu, s, o);
    __shared__ float ss[8];
    if ((threadIdx.x & 31) == 0) ss[threadIdx.x >> 5] = s;
    __syncthreads();
    if (threadIdx.x < 8) {
        s = ss[threadIdx.x];
        #pragma unroll
        for (int o = 4; o; o >>= 1) s += __shfl_down_sync(0xffu, s, o);
        if (threadIdx.x == 0) atomicAdd(&g_sum[b], s);
    }
}

// grid = BB * 64 blocks, 256 threads. Each thread produces one float4 of
// output in each of the 3 channel planes (same (h, w0..w0+3)).
__global__ void __launch_bounds__(256) transform_kernel(
    const float* __restrict__ imgs,
    const float* __restrict__ br,  const float* __restrict__ sat,
    const float* __restrict__ con, const int* __restrict__ tx,
    const int* __restrict__ ty,    const int* __restrict__ cx,
    const int* __restrict__ cy,    float* __restrict__ out)
{
    const int blocks_per_b = HW / (4 * 256);          // 64
    int b    = blockIdx.x / blocks_per_b;
    int blk  = blockIdx.x % blocks_per_b;
    int idx4 = blk * 256 + threadIdx.x;               // float4 index in plane
    int h    = idx4 >> 6;                             // 64 float4 per row
    int w0   = (idx4 & 63) << 2;

    // Per-image affine coefficients
    float a  = sat[b] * 2.0f;
    float k  = con[b] + 0.5f;
    float Af = k * a;
    float Bf = k * (1.0f - a);
    float M0 = g_sum[b] * (1.0f / (float)CHW);
    float Cf = (1.0f - k) * M0 + (br[b] - 0.5f);

    int txs = tx[b] - SHIFT;
    int tys = ty[b] - SHIFT;
    int cxv = cx[b], cyv = cy[b];
    int xlo = max(0, cxv - 64), xhi = min(HH - 1, cxv + 63);
    int ylo = max(0, cyv - 64), yhi = min(WW - 1, cyv + 63);

    int  sh       = h + txs;
    bool rowvalid = (sh >= 0) & (sh < HH);
    bool rowcut   = (h >= xlo) & (h <= xhi);
    int  sh_c     = min(max(sh, 0), HH - 1);          // safe address even when invalid

    const float* src = imgs + (size_t)b * CHW + (size_t)sh_c * WW;

    float o0[4], o1[4], o2[4];
    #pragma unroll
    for (int j = 0; j < 4; j++) {
        int  w  = w0 + j;
        int  sw = w + tys;
        bool valid = rowvalid & (sw >= 0) & (sw < WW)
                   & !(rowcut & (w >= ylo) & (w <= yhi));
        int sw_c = min(max(sw, 0), WW - 1);
        if (valid) {
            float v0 = __ldg(src + sw_c);
            float v1 = __ldg(src + HW + sw_c);
            float v2 = __ldg(src + 2 * HW + sw_c);
            float m  = (v0 + v1 + v2) * (1.0f / 3.0f);
            float bm = fmaf(Bf, m, Cf);
            o0[j] = fmaf(Af, v0, bm);
            o1[j] = fmaf(Af, v1, bm);
            o2[j] = fmaf(Af, v2, bm);
        } else {
            o0[j] = 0.f; o1[j] = 0.f; o2[j] = 0.f;
        }
    }

    float* dst = out + (size_t)b * CHW + (size_t)h * WW + w0;
    *(float4*)(dst)          = make_float4(o0[0], o0[1], o0[2], o0[3]);
    *(float4*)(dst + HW)     = make_float4(o1[0], o1[1], o1[2], o1[3]);
    *(float4*)(dst + 2 * HW) = make_float4(o2[0], o2[1], o2[2], o2[3]);
}

extern "C" void kernel_launch(void* const* d_in, const int* in_sizes, int n_in,
                              void* d_out, int out_size)
{
    const float* imgs = (const float*)d_in[0];
    const float* br   = (const float*)d_in[1];
    const float* sat  = (const float*)d_in[2];
    const float* con  = (const float*)d_in[3];
    const int*   tx   = (const int*)d_in[4];
    const int*   ty   = (const int*)d_in[5];
    const int*   cx   = (const int*)d_in[6];
    const int*   cy   = (const int*)d_in[7];
    float*       out  = (float*)d_out;

    zero_sums_kernel<<<1, 128>>>();
    reduce_kernel<<<BB * RBLKS, 256>>>(imgs);
    transform_kernel<<<BB * (HW / 1024), 256>>>(imgs, br, sat, con,
                                                tx, ty, cx, cy, out);
}

// round 2
// speedup vs baseline: 1.0256x; 1.0256x over previous
#include <cuda_runtime.h>

#define BB 128
#define CC 3
#define HH 256
#define WW 256
#define SHIFT 32
#define HW (HH*WW)      // 65536
#define CHW (CC*HW)     // 196608
#define RBLKS 32        // partial-sum blocks per image

__device__ float g_part[BB * RBLKS];

// grid = BB*RBLKS blocks, 256 threads. Each block reduces a contiguous chunk
// of one image and writes ONE partial sum (no atomics, no zero pass needed).
__global__ void __launch_bounds__(256) reduce_kernel(const float* __restrict__ imgs) {
    int b   = blockIdx.x / RBLKS;
    int blk = blockIdx.x % RBLKS;
    const float4* p = (const float4*)(imgs + (size_t)b * CHW);
    const int per_blk = (CHW / 4) / RBLKS;   // 1536 float4 per block
    int base = blk * per_blk;
    float s = 0.f;
    #pragma unroll 6
    for (int i = threadIdx.x; i < per_blk; i += 256) {
        float4 v = p[base + i];
        s += (v.x + v.y) + (v.z + v.w);
    }
    #pragma unroll
    for (int o = 16; o; o >>= 1) s += __shfl_down_sync(0xffffffffu, s, o);
    __shared__ float ss[8];
    if ((threadIdx.x & 31) == 0) ss[threadIdx.x >> 5] = s;
    __syncthreads();
    if (threadIdx.x < 8) {
        s = ss[threadIdx.x];
        #pragma unroll
        for (int o = 4; o; o >>= 1) s += __shfl_down_sync(0xffu, s, o);
        if (threadIdx.x == 0) g_part[blockIdx.x] = s;
    }
}

// grid = BB * 64 blocks, 256 threads. Each thread produces one float4 of
// output in each of the 3 channel planes (same (h, w0..w0+3)).
// Output stores are cache-streaming (__stcs) so the 100MB of output does not
// evict the input image data from L2 — transform reads stay L2-resident.
__global__ void __launch_bounds__(256) transform_kernel(
    const float* __restrict__ imgs,
    const float* __restrict__ br,  const float* __restrict__ sat,
    const float* __restrict__ con, const int* __restrict__ tx,
    const int* __restrict__ ty,    const int* __restrict__ cx,
    const int* __restrict__ cy,    float* __restrict__ out)
{
    const int blocks_per_b = HW / (4 * 256);          // 64
    int b    = blockIdx.x / blocks_per_b;
    int blk  = blockIdx.x % blocks_per_b;
    int idx4 = blk * 256 + threadIdx.x;               // float4 index in plane
    int h    = idx4 >> 6;                             // 64 float4 per row
    int w0   = (idx4 & 63) << 2;

    // One warp sums this image's 32 partials (L2-broadcast hits).
    __shared__ float sM0;
    if (threadIdx.x < 32) {
        float s = g_part[b * RBLKS + threadIdx.x];
        #pragma unroll
        for (int o = 16; o; o >>= 1) s += __shfl_down_sync(0xffffffffu, s, o);
        if (threadIdx.x == 0) sM0 = s * (1.0f / (float)CHW);
    }
    __syncthreads();

    // Per-image affine coefficients: out = Af*v + Bf*channel_mean + Cf
    float a  = sat[b] * 2.0f;
    float k  = con[b] + 0.5f;
    float Af = k * a;
    float Bf = k * (1.0f - a);
    float Cf = (1.0f - k) * sM0 + (br[b] - 0.5f);

    int txs = tx[b] - SHIFT;
    int tys = ty[b] - SHIFT;
    int cxv = cx[b], cyv = cy[b];
    int xlo = max(0, cxv - 64), xhi = min(HH - 1, cxv + 63);
    int ylo = max(0, cyv - 64), yhi = min(WW - 1, cyv + 63);

    int  sh       = h + txs;
    bool rowvalid = (sh >= 0) & (sh < HH);
    bool rowcut   = (h >= xlo) & (h <= xhi);
    int  sh_c     = min(max(sh, 0), HH - 1);          // safe address even when invalid

    const float* src = imgs + (size_t)b * CHW + (size_t)sh_c * WW;

    float o0[4], o1[4], o2[4];
    #pragma unroll
    for (int j = 0; j < 4; j++) {
        int  w  = w0 + j;
        int  sw = w + tys;
        bool valid = rowvalid & (sw >= 0) & (sw < WW)
                   & !(rowcut & (w >= ylo) & (w <= yhi));
        int sw_c = min(max(sw, 0), WW - 1);
        if (valid) {
            float v0 = __ldg(src + sw_c);
            float v1 = __ldg(src + HW + sw_c);
            float v2 = __ldg(src + 2 * HW + sw_c);
            float m  = (v0 + v1 + v2) * (1.0f / 3.0f);
            float bm = fmaf(Bf, m, Cf);
            o0[j] = fmaf(Af, v0, bm);
            o1[j] = fmaf(Af, v1, bm);
            o2[j] = fmaf(Af, v2, bm);
        } else {
            o0[j] = 0.f; o1[j] = 0.f; o2[j] = 0.f;
        }
    }

    float* dst = out + (size_t)b * CHW + (size_t)h * WW + w0;
    __stcs((float4*)(dst),          make_float4(o0[0], o0[1], o0[2], o0[3]));
    __stcs((float4*)(dst + HW),     make_float4(o1[0], o1[1], o1[2], o1[3]));
    __stcs((float4*)(dst + 2 * HW), make_float4(o2[0], o2[1], o2[2], o2[3]));
}

extern "C" void kernel_launch(void* const* d_in, const int* in_sizes, int n_in,
                              void* d_out, int out_size)
{
    const float* imgs = (const float*)d_in[0];
    const float* br   = (const float*)d_in[1];
    const float* sat  = (const float*)d_in[2];
    const float* con  = (const float*)d_in[3];
    const int*   tx   = (const int*)d_in[4];
    const int*   ty   = (const int*)d_in[5];
    const int*   cx   = (const int*)d_in[6];
    const int*   cy   = (const int*)d_in[7];
    float*       out  = (float*)d_out;

    reduce_kernel<<<BB * RBLKS, 256>>>(imgs);
    transform_kernel<<<BB * (HW / 1024), 256>>>(imgs, br, sat, con,
                                                tx, ty, cx, cy, out);
}